// round 15
// baseline (speedup 1.0000x reference)
#include <cuda_runtime.h>
#include <cstdint>

#define B_  2
#define S_  2048
#define D_  2048
#define H_  16
#define HD_ 128
#define M_  (B_*S_)    // 4096 rows
#define BH_ (B_*H_)    // 32
#define NCH 16         // chunks of 128 rows per (b,h)

// Scratch (device globals — no allocation allowed)
__device__ float g_Q[M_*D_];
__device__ float g_K[M_*D_];
__device__ float g_V[M_*D_];
__device__ float g_attn[M_*D_];
__device__ float g_rsum[BH_*S_];   // sum_{k>=i} exp(s_ik)
__device__ float g_ediag[BH_*S_];  // exp(s_ii)
__device__ float g_csum[BH_*NCH*HD_];

__device__ __forceinline__ uint32_t f2tf32(float f) {
    uint32_t r;
    asm("cvt.rna.tf32.f32 %0, %1;" : "=r"(r) : "f"(f));
    return r;
}

__device__ __forceinline__ void mma_tf32(float* d, const uint32_t* a, const uint32_t* b) {
    asm volatile(
        "mma.sync.aligned.m16n8k8.row.col.f32.tf32.tf32.f32 "
        "{%0,%1,%2,%3}, {%4,%5,%6,%7}, {%8,%9}, {%0,%1,%2,%3};"
        : "+f"(d[0]), "+f"(d[1]), "+f"(d[2]), "+f"(d[3])
        : "r"(a[0]), "r"(a[1]), "r"(a[2]), "r"(a[3]), "r"(b[0]), "r"(b[1]));
}

// exp(dot/sqrt(D)) on the FMA pipe: 2^(dot*C), C = log2(e)/sqrt(2048).
// rintf range reduction + deg-6 Taylor of 2^f on [-0.5,0.5] (rel err ~1.2e-7).
__device__ __forceinline__ float fexps(float dot) {
    float y = dot * 0.03187935813144613f;
    int   ni = __float2int_rn(y);
    float f  = y - (float)ni;
    float p  = 0.00015403530f;
    p = fmaf(p, f, 0.00133335581f);
    p = fmaf(p, f, 0.00961812911f);
    p = fmaf(p, f, 0.05550410866f);
    p = fmaf(p, f, 0.24022650700f);
    p = fmaf(p, f, 0.69314718056f);
    p = fmaf(p, f, 1.0f);
    return p * __int_as_float((127 + ni) << 23);
}

// ---------------------------------------------------------------------------
// tf32 mma.sync GEMM: C[m][n] = sum_k A[m][k]*Bw[n][k] + bias[n]
// 128x128 CTA tile, BK=16, double-buffered SMEM, 256 threads (8 warps),
// warp tile 64x32 = 4x4 m16n8k8 fragments, 2 k-steps per chunk.
// SMEM row stride 20 floats -> conflict-free fragment LDS (bank = 4r+c).
// 3 CTAs/SM: 6 warps/SMSP to hide LDS/HMMA latency; 512 CTAs -> 1.15 waves.
// ---------------------------------------------------------------------------
#define ASTRIDE 20
__global__ __launch_bounds__(256, 3)
void gemm_tc(const float* __restrict__ A, const float* __restrict__ Bw,
             const float* __restrict__ bias, float* __restrict__ C) {
    __shared__ __align__(16) float As[2][128 * ASTRIDE];
    __shared__ __align__(16) float Bs[2][128 * ASTRIDE];

    const int tid  = threadIdx.x;
    const int wid  = tid >> 5;
    const int lane = tid & 31;
    const int gid  = lane >> 2;      // groupID (0..7)
    const int tig  = lane & 3;       // thread-in-group (0..3)
    const int wm   = (wid & 1) * 64; // warp m offset
    const int wn   = (wid >> 1) * 32;// warp n offset
    const int m0   = blockIdx.y * 128, n0 = blockIdx.x * 128;

    const int lrow = tid >> 1;        // 0..127
    const int lcs  = (tid & 1) * 2;   // float4 slot 0 or 2

    const float* Ab = A  + (size_t)(m0 + lrow) * D_ + lcs * 4;
    const float* Bb = Bw + (size_t)(n0 + lrow) * D_ + lcs * 4;

    float4 va[2], vb[2];

#define LOAD_CHUNK(kt) do {                                                    \
    _Pragma("unroll")                                                          \
    for (int j = 0; j < 2; ++j) {                                              \
        va[j] = *(const float4*)(Ab + (kt) * 16 + j * 4);                      \
        vb[j] = *(const float4*)(Bb + (kt) * 16 + j * 4);                      \
    } } while (0)

#define STORE_CHUNK(stg) do {                                                  \
    _Pragma("unroll")                                                          \
    for (int j = 0; j < 2; ++j) {                                              \
        float* pa = &As[stg][lrow * ASTRIDE + (lcs + j) * 4];                  \
        float* pb = &Bs[stg][lrow * ASTRIDE + (lcs + j) * 4];                  \
        pa[0] = __uint_as_float(f2tf32(va[j].x));                              \
        pa[1] = __uint_as_float(f2tf32(va[j].y));                              \
        pa[2] = __uint_as_float(f2tf32(va[j].z));                              \
        pa[3] = __uint_as_float(f2tf32(va[j].w));                              \
        pb[0] = __uint_as_float(f2tf32(vb[j].x));                              \
        pb[1] = __uint_as_float(f2tf32(vb[j].y));                              \
        pb[2] = __uint_as_float(f2tf32(vb[j].z));                              \
        pb[3] = __uint_as_float(f2tf32(vb[j].w));                              \
    } } while (0)

    float acc[4][4][4];
#pragma unroll
    for (int mt = 0; mt < 4; ++mt)
#pragma unroll
        for (int nt = 0; nt < 4; ++nt)
#pragma unroll
            for (int q = 0; q < 4; ++q) acc[mt][nt][q] = 0.f;

    LOAD_CHUNK(0);
    STORE_CHUNK(0);
    __syncthreads();

    const int NCHUNK = D_ / 16;   // 128
    for (int c = 0; c < NCHUNK; ++c) {
        const int stg = c & 1;
        if (c + 1 < NCHUNK) LOAD_CHUNK(c + 1);   // overlaps MMA below

#pragma unroll
        for (int ks = 0; ks < 2; ++ks) {
            uint32_t af[4][4], bf[4][2];
            const int kc = ks * 8 + tig;
#pragma unroll
            for (int mt = 0; mt < 4; ++mt) {
                const int r = wm + mt * 16 + gid;
                af[mt][0] = __float_as_uint(As[stg][r * ASTRIDE + kc]);
                af[mt][1] = __float_as_uint(As[stg][(r + 8) * ASTRIDE + kc]);
                af[mt][2] = __float_as_uint(As[stg][r * ASTRIDE + kc + 4]);
                af[mt][3] = __float_as_uint(As[stg][(r + 8) * ASTRIDE + kc + 4]);
            }
#pragma unroll
            for (int nt = 0; nt < 4; ++nt) {
                const int n = wn + nt * 8 + gid;
                bf[nt][0] = __float_as_uint(Bs[stg][n * ASTRIDE + kc]);
                bf[nt][1] = __float_as_uint(Bs[stg][n * ASTRIDE + kc + 4]);
            }
#pragma unroll
            for (int mt = 0; mt < 4; ++mt)
#pragma unroll
                for (int nt = 0; nt < 4; ++nt)
                    mma_tf32(acc[mt][nt], af[mt], bf[nt]);
        }

        if (c + 1 < NCHUNK) {
            STORE_CHUNK((c + 1) & 1);   // opposite buffer from the one just read
            __syncthreads();
        }
    }

    // epilogue: + bias, write C
#pragma unroll
    for (int mt = 0; mt < 4; ++mt) {
        const int row0 = m0 + wm + mt * 16 + gid;
#pragma unroll
        for (int nt = 0; nt < 4; ++nt) {
            const int col = n0 + wn + nt * 8 + tig * 2;
            const float2 b2 = *(const float2*)(bias + col);
            float2 o0 = make_float2(acc[mt][nt][0] + b2.x, acc[mt][nt][1] + b2.y);
            float2 o1 = make_float2(acc[mt][nt][2] + b2.x, acc[mt][nt][3] + b2.y);
            *(float2*)(C + (size_t)row0 * D_ + col)       = o0;
            *(float2*)(C + (size_t)(row0 + 8) * D_ + col) = o1;
        }
    }
#undef LOAD_CHUNK
#undef STORE_CHUNK
}

// ---------------------------------------------------------------------------
// Tensor-core scores: per (b,h), per 64-row tile, compute
// r_i = sum_{k>=i} exp(s_ik/sqrt(D)) and e_i = exp(s_ii) via tf32 mma.
// Q tile (64x128) resident in smem; K tiles DOUBLE-BUFFERED (one sync/iter).
// Only the first k-tile is triangular; later tiles are fully unmasked.
// Row sums accumulate in registers; one shuffle+atomic reduction at the end.
// 256 threads = 8 warps; warp tile 16(i) x 32(k).
// ---------------------------------------------------------------------------
#define QSTRIDE 132
#define SCORES_SMEM ((64*QSTRIDE*3 + 64) * 4)
__global__ __launch_bounds__(256)
void scores_mma(const float* __restrict__ Q, const float* __restrict__ Km) {
    extern __shared__ float sms[];
    float* qs  = sms;                        // 64 x 132
    float* ks0 = sms + 64 * QSTRIDE;         // 2 x (64 x 132)
    float* rowsum = sms + 64 * QSTRIDE * 3;  // 64

    const int tid  = threadIdx.x;
    const int wid  = tid >> 5;
    const int lane = tid & 31;
    const int gid  = lane >> 2;
    const int tig  = lane & 3;
    const int wm   = (wid & 3) * 16;   // warp i offset (0..48)
    const int wn   = (wid >> 2) * 32;  // warp k offset (0 or 32)

    const int bh = blockIdx.y;
    const int b  = bh >> 4, h = bh & 15;
    const int r0 = blockIdx.x * 64;
    const int t0 = r0 >> 6;

    const float* Qb = Q  + (size_t)(b * S_) * D_ + h * HD_;
    const float* Kb = Km + (size_t)(b * S_) * D_ + h * HD_;

    const int lrow = tid >> 2;    // 0..63
    const int lc   = tid & 3;     // float4 lane within row group

    // Q tile -> smem (tf32-rounded)
#pragma unroll
    for (int j = 0; j < 8; ++j) {
        float4 f = *(const float4*)(Qb + (size_t)(r0 + lrow) * D_ + lc * 4 + 16 * j);
        float* p = &qs[lrow * QSTRIDE + lc * 4 + 16 * j];
        p[0] = __uint_as_float(f2tf32(f.x));
        p[1] = __uint_as_float(f2tf32(f.y));
        p[2] = __uint_as_float(f2tf32(f.z));
        p[3] = __uint_as_float(f2tf32(f.w));
    }
    if (tid < 64) rowsum[tid] = 0.f;

    float4 rk[8];
#define LOAD_KREGS(kt) do {                                                        \
    _Pragma("unroll")                                                              \
    for (int j = 0; j < 8; ++j)                                                    \
        rk[j] = *(const float4*)(Kb + (size_t)((kt)*64 + lrow) * D_ + lc*4 + 16*j);\
    } while (0)

#define STORE_KREGS(buf) do {                                                      \
    float* kb = ks0 + (buf) * 64 * QSTRIDE;                                        \
    _Pragma("unroll")                                                              \
    for (int j = 0; j < 8; ++j) {                                                  \
        float* p = &kb[lrow * QSTRIDE + lc * 4 + 16 * j];                          \
        p[0] = __uint_as_float(f2tf32(rk[j].x));                                   \
        p[1] = __uint_as_float(f2tf32(rk[j].y));                                   \
        p[2] = __uint_as_float(f2tf32(rk[j].z));                                   \
        p[3] = __uint_as_float(f2tf32(rk[j].w));                                   \
    } } while (0)

    LOAD_KREGS(t0);
    STORE_KREGS(0);
    __syncthreads();

    float rs0 = 0.f, rs1 = 0.f;
    const int gi0 = r0 + wm + gid;
    const int gi1 = gi0 + 8;

    for (int kt = t0; kt < S_ / 64; ++kt) {
        const int k0 = kt * 64;
        const float* kbuf = ks0 + ((kt - t0) & 1) * 64 * QSTRIDE;
        if (kt + 1 < S_ / 64) LOAD_KREGS(kt + 1);   // overlaps MMA + exp below

        float acc[4][4];
#pragma unroll
        for (int nt = 0; nt < 4; ++nt)
#pragma unroll
            for (int q = 0; q < 4; ++q) acc[nt][q] = 0.f;

#pragma unroll
        for (int kk = 0; kk < 16; ++kk) {
            const int kc = kk * 8 + tig;
            uint32_t af[4], bf[4][2];
            af[0] = __float_as_uint(qs[(wm + gid) * QSTRIDE + kc]);
            af[1] = __float_as_uint(qs[(wm + gid + 8) * QSTRIDE + kc]);
            af[2] = __float_as_uint(qs[(wm + gid) * QSTRIDE + kc + 4]);
            af[3] = __float_as_uint(qs[(wm + gid + 8) * QSTRIDE + kc + 4]);
#pragma unroll
            for (int nt = 0; nt < 4; ++nt) {
                const int n = wn + nt * 8 + gid;
                bf[nt][0] = __float_as_uint(kbuf[n * QSTRIDE + kc]);
                bf[nt][1] = __float_as_uint(kbuf[n * QSTRIDE + kc + 4]);
            }
#pragma unroll
            for (int nt = 0; nt < 4; ++nt)
                mma_tf32(acc[nt], af, bf[nt]);
        }

        if (kt == t0) {
            // triangular tile: mask, capture diagonal
#pragma unroll
            for (int nt = 0; nt < 4; ++nt) {
                const int gk = k0 + wn + nt * 8 + tig * 2;
                float e00 = (gk     >= gi0) ? fexps(acc[nt][0]) : 0.f;
                float e01 = (gk + 1 >= gi0) ? fexps(acc[nt][1]) : 0.f;
                float e10 = (gk     >= gi1) ? fexps(acc[nt][2]) : 0.f;
                float e11 = (gk + 1 >= gi1) ? fexps(acc[nt][3]) : 0.f;
                if (gk     == gi0) g_ediag[bh * S_ + gi0] = e00;
                if (gk + 1 == gi0) g_ediag[bh * S_ + gi0] = e01;
                if (gk     == gi1) g_ediag[bh * S_ + gi1] = e10;
                if (gk + 1 == gi1) g_ediag[bh * S_ + gi1] = e11;
                rs0 += e00 + e01;
                rs1 += e10 + e11;
            }
        } else {
#pragma unroll
            for (int nt = 0; nt < 4; ++nt) {
                rs0 += fexps(acc[nt][0]) + fexps(acc[nt][1]);
                rs1 += fexps(acc[nt][2]) + fexps(acc[nt][3]);
            }
        }

        if (kt + 1 < S_ / 64) {
            STORE_KREGS((kt - t0 + 1) & 1);   // other buffer; all warps already
            __syncthreads();                   // done reading it (prev sync)
        }
    }

    // reduce across the 4 lanes (tig) of each row group
    rs0 += __shfl_down_sync(0xffffffffu, rs0, 2, 4);
    rs0 += __shfl_down_sync(0xffffffffu, rs0, 1, 4);
    rs1 += __shfl_down_sync(0xffffffffu, rs1, 2, 4);
    rs1 += __shfl_down_sync(0xffffffffu, rs1, 1, 4);
    if (tig == 0) {
        atomicAdd(&rowsum[wm + gid],     rs0);
        atomicAdd(&rowsum[wm + gid + 8], rs1);
    }
    __syncthreads();
    if (tid < 64) g_rsum[bh * S_ + r0 + tid] = rowsum[tid];
#undef LOAD_KREGS
#undef STORE_KREGS
}

// ---------------------------------------------------------------------------
// Prefix-scan of V per (b,h,d):  attn_i = (sum_{j<i} v_j + e_i*v_i) / (i + r_i)
// ---------------------------------------------------------------------------
__global__ void chunk_sum_kernel(const float* __restrict__ V) {
    const int bh = blockIdx.y, ch = blockIdx.x, d = threadIdx.x;
    const int b = bh >> 4, h = bh & 15;
    const float* Vb = V + (size_t)(b * S_ + ch * 128) * D_ + h * HD_ + d;
    float s = 0.f;
#pragma unroll 8
    for (int i = 0; i < 128; ++i) s += Vb[(size_t)i * D_];
    g_csum[(bh * NCH + ch) * HD_ + d] = s;
}

__global__ void prefix_kernel() {
    const int bh = blockIdx.x, d = threadIdx.x;
    float run = 0.f;
#pragma unroll
    for (int ch = 0; ch < NCH; ++ch) {
        const int idx = (bh * NCH + ch) * HD_ + d;
        float s = g_csum[idx];
        g_csum[idx] = run;    // exclusive prefix
        run += s;
    }
}

__global__ void attn_kernel(const float* __restrict__ V, float* __restrict__ attn) {
    const int bh = blockIdx.y, ch = blockIdx.x, d = threadIdx.x;
    const int b = bh >> 4, h = bh & 15;
    float run = g_csum[(bh * NCH + ch) * HD_ + d];
    const float* Vb = V    + (size_t)(b * S_ + ch * 128) * D_ + h * HD_ + d;
    float*       Ab = attn + (size_t)(b * S_ + ch * 128) * D_ + h * HD_ + d;
#pragma unroll 4
    for (int i = 0; i < 128; ++i) {
        const int gi = ch * 128 + i;
        float v = Vb[(size_t)i * D_];
        float z = (float)gi + g_rsum[bh * S_ + gi];
        Ab[(size_t)i * D_] = (run + g_ediag[bh * S_ + gi] * v) / z;
        run += v;
    }
}

// ---------------------------------------------------------------------------
extern "C" void kernel_launch(void* const* d_in, const int* in_sizes, int n_in,
                              void* d_out, int out_size) {
    (void)in_sizes; (void)n_in; (void)out_size;
    const float* x  = (const float*)d_in[0];
    const float* wq = (const float*)d_in[1];
    const float* bq = (const float*)d_in[2];
    const float* wk = (const float*)d_in[3];
    const float* bk = (const float*)d_in[4];
    const float* wv = (const float*)d_in[5];
    const float* bv = (const float*)d_in[6];
    const float* wo = (const float*)d_in[7];
    const float* bo = (const float*)d_in[8];
    float* out = (float*)d_out;

    float *Q, *K, *V, *attn;
    cudaGetSymbolAddress((void**)&Q,    g_Q);
    cudaGetSymbolAddress((void**)&K,    g_K);
    cudaGetSymbolAddress((void**)&V,    g_V);
    cudaGetSymbolAddress((void**)&attn, g_attn);

    cudaFuncSetAttribute(scores_mma, cudaFuncAttributeMaxDynamicSharedMemorySize,
                         SCORES_SMEM);

    dim3 gg(D_ / 128, M_ / 128);   // (16, 32)
    gemm_tc<<<gg, 256>>>(x, wq, bq, Q);
    gemm_tc<<<gg, 256>>>(x, wk, bk, K);
    gemm_tc<<<gg, 256>>>(x, wv, bv, V);

    scores_mma<<<dim3(S_ / 64, BH_), 256, SCORES_SMEM>>>(Q, K);

    chunk_sum_kernel<<<dim3(NCH, BH_), HD_>>>(V);
    prefix_kernel<<<BH_, HD_>>>();
    attn_kernel<<<dim3(NCH, BH_), HD_>>>(V, attn);

    gemm_tc<<<gg, 256>>>(attn, wo, bo, out);
}

// round 16
// speedup vs baseline: 2.8318x; 2.8318x over previous
#include <cuda_runtime.h>
#include <cstdint>

#define B_  2
#define S_  2048
#define D_  2048
#define H_  16
#define HD_ 128
#define M_  (B_*S_)    // 4096 rows
#define BH_ (B_*H_)    // 32
#define NCH 16         // chunks of 128 rows per (b,h)

// Scratch (device globals — no allocation allowed)
__device__ float g_Q[M_*D_];
__device__ float g_K[M_*D_];
__device__ float g_V[M_*D_];
__device__ float g_attn[M_*D_];
__device__ float g_rsum[BH_*S_];   // sum_{k>=i} exp(s_ik)
__device__ float g_ediag[BH_*S_];  // exp(s_ii)
__device__ float g_csum[BH_*NCH*HD_];

__device__ __forceinline__ uint32_t smem_u32(const void* p) {
    uint32_t a;
    asm("{ .reg .u64 t; cvta.to.shared.u64 t, %1; cvt.u32.u64 %0, t; }"
        : "=r"(a) : "l"(p));
    return a;
}
__device__ __forceinline__ uint32_t f2tf32(float f) {
    uint32_t r;
    asm("cvt.rna.tf32.f32 %0, %1;" : "=r"(r) : "f"(f));
    return r;
}
__device__ __forceinline__ void cp16(uint32_t dst, const float* src) {
    asm volatile("cp.async.cg.shared.global [%0], [%1], 16;"
                 :: "r"(dst), "l"(src));
}
#define CP_COMMIT() asm volatile("cp.async.commit_group;" ::: "memory")
#define CP_WAIT2()  asm volatile("cp.async.wait_group 2;" ::: "memory")
#define CP_WAIT0()  asm volatile("cp.async.wait_group 0;" ::: "memory")

__device__ __forceinline__ void mma_tf32(float* d, const uint32_t* a, const uint32_t* b) {
    asm volatile(
        "mma.sync.aligned.m16n8k8.row.col.f32.tf32.tf32.f32 "
        "{%0,%1,%2,%3}, {%4,%5,%6,%7}, {%8,%9}, {%0,%1,%2,%3};"
        : "+f"(d[0]), "+f"(d[1]), "+f"(d[2]), "+f"(d[3])
        : "r"(a[0]), "r"(a[1]), "r"(a[2]), "r"(a[3]), "r"(b[0]), "r"(b[1]));
}

// exp(dot/sqrt(D)) on the FMA pipe: 2^(dot*C), C = log2(e)/sqrt(2048).
__device__ __forceinline__ float fexps(float dot) {
    float y = dot * 0.03187935813144613f;
    int   ni = __float2int_rn(y);
    float f  = y - (float)ni;
    float p  = 0.00015403530f;
    p = fmaf(p, f, 0.00133335581f);
    p = fmaf(p, f, 0.00961812911f);
    p = fmaf(p, f, 0.05550410866f);
    p = fmaf(p, f, 0.24022650700f);
    p = fmaf(p, f, 0.69314718056f);
    p = fmaf(p, f, 1.0f);
    return p * __int_as_float((127 + ni) << 23);
}

// ---------------------------------------------------------------------------
// tf32 mma.sync GEMM with cp.async 4-stage pipeline.
// C[m][n] = sum_k A[m][k]*Bw[n][k] + bias[n]
// 128x128 CTA tile, BK=16, 256 threads (8 warps), warp tile 64x32.
// cp.async.cg copies raw fp32 global->smem (3 chunks in flight); tf32
// rounding happens at fragment load (fma pipe, hidden under HMMA).
// SMEM row stride 20 floats -> conflict-free fragment LDS.
// ---------------------------------------------------------------------------
#define ASTRIDE 20
#define GSTAGES 4
#define STAGEF  (128*ASTRIDE)                    // floats per operand per stage
#define GEMM_SMEM_BYTES (GSTAGES * 2 * STAGEF * 4)  // 81920
__global__ __launch_bounds__(256)
void gemm_tc(const float* __restrict__ A, const float* __restrict__ Bw,
             const float* __restrict__ bias, float* __restrict__ C) {
    extern __shared__ __align__(16) float smd[];
    const uint32_t smb = smem_u32(smd);

    const int tid  = threadIdx.x;
    const int wid  = tid >> 5;
    const int lane = tid & 31;
    const int gid  = lane >> 2;      // groupID (0..7)
    const int tig  = lane & 3;       // thread-in-group (0..3)
    const int wm   = (wid & 1) * 64; // warp m offset
    const int wn   = (wid >> 1) * 32;// warp n offset
    const int m0   = blockIdx.y * 128, n0 = blockIdx.x * 128;

    const int lrow = tid >> 1;        // 0..127
    const int lcs  = (tid & 1) * 2;   // float4 slot 0 or 2

    const float* Asrc = A  + (size_t)(m0 + lrow) * D_ + lcs * 4;
    const float* Bsrc = Bw + (size_t)(n0 + lrow) * D_ + lcs * 4;
    const uint32_t adst = smb + (uint32_t)(lrow * ASTRIDE + lcs * 4) * 4;
    const uint32_t bdst = adst + STAGEF * 4;
    const uint32_t stg_bytes = 2 * STAGEF * 4;    // 20480

#define ISSUE(kt, stg) do {                                                    \
    uint32_t sb = (uint32_t)(stg) * stg_bytes;                                 \
    cp16(adst + sb,      Asrc + (kt) * 16);                                    \
    cp16(adst + sb + 16, Asrc + (kt) * 16 + 4);                                \
    cp16(bdst + sb,      Bsrc + (kt) * 16);                                    \
    cp16(bdst + sb + 16, Bsrc + (kt) * 16 + 4);                                \
    } while (0)

    float acc[4][4][4];
#pragma unroll
    for (int mt = 0; mt < 4; ++mt)
#pragma unroll
        for (int nt = 0; nt < 4; ++nt)
#pragma unroll
            for (int q = 0; q < 4; ++q) acc[mt][nt][q] = 0.f;

    // prologue: chunks 0..2 into stages 0..2 (3 groups in flight)
    ISSUE(0, 0); CP_COMMIT();
    ISSUE(1, 1); CP_COMMIT();
    ISSUE(2, 2); CP_COMMIT();

    const int NCHUNK = D_ / 16;   // 128
    for (int c = 0; c < NCHUNK; ++c) {
        if (c + 3 <= NCHUNK) { CP_WAIT2(); } else { CP_WAIT0(); }
        __syncthreads();
        // refill freed stage ((c-1)&3) with chunk c+3 — safe: sync above
        // guarantees all warps finished reading it (MMA of chunk c-1).
        if (c + 3 < NCHUNK) { ISSUE(c + 3, (c + 3) & 3); CP_COMMIT(); }

        const float* As_c = smd + (c & 3) * (2 * STAGEF);
        const float* Bs_c = As_c + STAGEF;
#pragma unroll
        for (int ks = 0; ks < 2; ++ks) {
            uint32_t af[4][4], bf[4][2];
            const int kc = ks * 8 + tig;
#pragma unroll
            for (int mt = 0; mt < 4; ++mt) {
                const int r = wm + mt * 16 + gid;
                af[mt][0] = f2tf32(As_c[r * ASTRIDE + kc]);
                af[mt][1] = f2tf32(As_c[(r + 8) * ASTRIDE + kc]);
                af[mt][2] = f2tf32(As_c[r * ASTRIDE + kc + 4]);
                af[mt][3] = f2tf32(As_c[(r + 8) * ASTRIDE + kc + 4]);
            }
#pragma unroll
            for (int nt = 0; nt < 4; ++nt) {
                const int n = wn + nt * 8 + gid;
                bf[nt][0] = f2tf32(Bs_c[n * ASTRIDE + kc]);
                bf[nt][1] = f2tf32(Bs_c[n * ASTRIDE + kc + 4]);
            }
#pragma unroll
            for (int mt = 0; mt < 4; ++mt)
#pragma unroll
                for (int nt = 0; nt < 4; ++nt)
                    mma_tf32(acc[mt][nt], af[mt], bf[nt]);
        }
    }

    // epilogue: + bias, write C
#pragma unroll
    for (int mt = 0; mt < 4; ++mt) {
        const int row0 = m0 + wm + mt * 16 + gid;
#pragma unroll
        for (int nt = 0; nt < 4; ++nt) {
            const int col = n0 + wn + nt * 8 + tig * 2;
            const float2 b2 = *(const float2*)(bias + col);
            float2 o0 = make_float2(acc[mt][nt][0] + b2.x, acc[mt][nt][1] + b2.y);
            float2 o1 = make_float2(acc[mt][nt][2] + b2.x, acc[mt][nt][3] + b2.y);
            *(float2*)(C + (size_t)row0 * D_ + col)       = o0;
            *(float2*)(C + (size_t)(row0 + 8) * D_ + col) = o1;
        }
    }
#undef ISSUE
}

// ---------------------------------------------------------------------------
// Tensor-core scores (R14 layout, double-buffered K): per (b,h), per 64-row
// tile, r_i = sum_{k>=i} exp(s_ik/sqrt(D)), e_i = exp(s_ii) via tf32 mma.
// ---------------------------------------------------------------------------
#define QSTRIDE 132
#define SCORES_SMEM ((64*QSTRIDE*3 + 64) * 4)
__global__ __launch_bounds__(256)
void scores_mma(const float* __restrict__ Q, const float* __restrict__ Km) {
    extern __shared__ float sms[];
    float* qs  = sms;                        // 64 x 132
    float* ks0 = sms + 64 * QSTRIDE;         // 2 x (64 x 132)
    float* rowsum = sms + 64 * QSTRIDE * 3;  // 64

    const int tid  = threadIdx.x;
    const int wid  = tid >> 5;
    const int lane = tid & 31;
    const int gid  = lane >> 2;
    const int tig  = lane & 3;
    const int wm   = (wid & 3) * 16;   // warp i offset (0..48)
    const int wn   = (wid >> 2) * 32;  // warp k offset (0 or 32)

    const int bh = blockIdx.y;
    const int b  = bh >> 4, h = bh & 15;
    const int r0 = blockIdx.x * 64;
    const int t0 = r0 >> 6;

    const float* Qb = Q  + (size_t)(b * S_) * D_ + h * HD_;
    const float* Kb = Km + (size_t)(b * S_) * D_ + h * HD_;

    const int lrow = tid >> 2;    // 0..63
    const int lc   = tid & 3;     // float4 lane within row group

#pragma unroll
    for (int j = 0; j < 8; ++j) {
        float4 f = *(const float4*)(Qb + (size_t)(r0 + lrow) * D_ + lc * 4 + 16 * j);
        float* p = &qs[lrow * QSTRIDE + lc * 4 + 16 * j];
        p[0] = __uint_as_float(f2tf32(f.x));
        p[1] = __uint_as_float(f2tf32(f.y));
        p[2] = __uint_as_float(f2tf32(f.z));
        p[3] = __uint_as_float(f2tf32(f.w));
    }
    if (tid < 64) rowsum[tid] = 0.f;

    float4 rk[8];
#define LOAD_KREGS(kt) do {                                                        \
    _Pragma("unroll")                                                              \
    for (int j = 0; j < 8; ++j)                                                    \
        rk[j] = *(const float4*)(Kb + (size_t)((kt)*64 + lrow) * D_ + lc*4 + 16*j);\
    } while (0)

#define STORE_KREGS(buf) do {                                                      \
    float* kb = ks0 + (buf) * 64 * QSTRIDE;                                        \
    _Pragma("unroll")                                                              \
    for (int j = 0; j < 8; ++j) {                                                  \
        float* p = &kb[lrow * QSTRIDE + lc * 4 + 16 * j];                          \
        p[0] = __uint_as_float(f2tf32(rk[j].x));                                   \
        p[1] = __uint_as_float(f2tf32(rk[j].y));                                   \
        p[2] = __uint_as_float(f2tf32(rk[j].z));                                   \
        p[3] = __uint_as_float(f2tf32(rk[j].w));                                   \
    } } while (0)

    LOAD_KREGS(t0);
    STORE_KREGS(0);
    __syncthreads();

    float rs0 = 0.f, rs1 = 0.f;
    const int gi0 = r0 + wm + gid;
    const int gi1 = gi0 + 8;

    for (int kt = t0; kt < S_ / 64; ++kt) {
        const int k0 = kt * 64;
        const float* kbuf = ks0 + ((kt - t0) & 1) * 64 * QSTRIDE;
        if (kt + 1 < S_ / 64) LOAD_KREGS(kt + 1);   // overlaps MMA + exp below

        float acc[4][4];
#pragma unroll
        for (int nt = 0; nt < 4; ++nt)
#pragma unroll
            for (int q = 0; q < 4; ++q) acc[nt][q] = 0.f;

#pragma unroll
        for (int kk = 0; kk < 16; ++kk) {
            const int kc = kk * 8 + tig;
            uint32_t af[4], bf[4][2];
            af[0] = __float_as_uint(qs[(wm + gid) * QSTRIDE + kc]);
            af[1] = __float_as_uint(qs[(wm + gid + 8) * QSTRIDE + kc]);
            af[2] = __float_as_uint(qs[(wm + gid) * QSTRIDE + kc + 4]);
            af[3] = __float_as_uint(qs[(wm + gid + 8) * QSTRIDE + kc + 4]);
#pragma unroll
            for (int nt = 0; nt < 4; ++nt) {
                const int n = wn + nt * 8 + gid;
                bf[nt][0] = __float_as_uint(kbuf[n * QSTRIDE + kc]);
                bf[nt][1] = __float_as_uint(kbuf[n * QSTRIDE + kc + 4]);
            }
#pragma unroll
            for (int nt = 0; nt < 4; ++nt)
                mma_tf32(acc[nt], af, bf[nt]);
        }

        if (kt == t0) {
            // triangular tile: mask, capture diagonal
#pragma unroll
            for (int nt = 0; nt < 4; ++nt) {
                const int gk = k0 + wn + nt * 8 + tig * 2;
                float e00 = (gk     >= gi0) ? fexps(acc[nt][0]) : 0.f;
                float e01 = (gk + 1 >= gi0) ? fexps(acc[nt][1]) : 0.f;
                float e10 = (gk     >= gi1) ? fexps(acc[nt][2]) : 0.f;
                float e11 = (gk + 1 >= gi1) ? fexps(acc[nt][3]) : 0.f;
                if (gk     == gi0) g_ediag[bh * S_ + gi0] = e00;
                if (gk + 1 == gi0) g_ediag[bh * S_ + gi0] = e01;
                if (gk     == gi1) g_ediag[bh * S_ + gi1] = e10;
                if (gk + 1 == gi1) g_ediag[bh * S_ + gi1] = e11;
                rs0 += e00 + e01;
                rs1 += e10 + e11;
            }
        } else {
#pragma unroll
            for (int nt = 0; nt < 4; ++nt) {
                rs0 += fexps(acc[nt][0]) + fexps(acc[nt][1]);
                rs1 += fexps(acc[nt][2]) + fexps(acc[nt][3]);
            }
        }

        if (kt + 1 < S_ / 64) {
            STORE_KREGS((kt - t0 + 1) & 1);
            __syncthreads();
        }
    }

    rs0 += __shfl_down_sync(0xffffffffu, rs0, 2, 4);
    rs0 += __shfl_down_sync(0xffffffffu, rs0, 1, 4);
    rs1 += __shfl_down_sync(0xffffffffu, rs1, 2, 4);
    rs1 += __shfl_down_sync(0xffffffffu, rs1, 1, 4);
    if (tig == 0) {
        atomicAdd(&rowsum[wm + gid],     rs0);
        atomicAdd(&rowsum[wm + gid + 8], rs1);
    }
    __syncthreads();
    if (tid < 64) g_rsum[bh * S_ + r0 + tid] = rowsum[tid];
#undef LOAD_KREGS
#undef STORE_KREGS
}

// ---------------------------------------------------------------------------
// Prefix-scan of V per (b,h,d):  attn_i = (sum_{j<i} v_j + e_i*v_i) / (i + r_i)
// ---------------------------------------------------------------------------
__global__ void chunk_sum_kernel(const float* __restrict__ V) {
    const int bh = blockIdx.y, ch = blockIdx.x, d = threadIdx.x;
    const int b = bh >> 4, h = bh & 15;
    const float* Vb = V + (size_t)(b * S_ + ch * 128) * D_ + h * HD_ + d;
    float s = 0.f;
#pragma unroll 8
    for (int i = 0; i < 128; ++i) s += Vb[(size_t)i * D_];
    g_csum[(bh * NCH + ch) * HD_ + d] = s;
}

__global__ void prefix_kernel() {
    const int bh = blockIdx.x, d = threadIdx.x;
    float run = 0.f;
#pragma unroll
    for (int ch = 0; ch < NCH; ++ch) {
        const int idx = (bh * NCH + ch) * HD_ + d;
        float s = g_csum[idx];
        g_csum[idx] = run;    // exclusive prefix
        run += s;
    }
}

__global__ void attn_kernel(const float* __restrict__ V, float* __restrict__ attn) {
    const int bh = blockIdx.y, ch = blockIdx.x, d = threadIdx.x;
    const int b = bh >> 4, h = bh & 15;
    float run = g_csum[(bh * NCH + ch) * HD_ + d];
    const float* Vb = V    + (size_t)(b * S_ + ch * 128) * D_ + h * HD_ + d;
    float*       Ab = attn + (size_t)(b * S_ + ch * 128) * D_ + h * HD_ + d;
#pragma unroll 4
    for (int i = 0; i < 128; ++i) {
        const int gi = ch * 128 + i;
        float v = Vb[(size_t)i * D_];
        float z = (float)gi + g_rsum[bh * S_ + gi];
        Ab[(size_t)i * D_] = (run + g_ediag[bh * S_ + gi] * v) / z;
        run += v;
    }
}

// ---------------------------------------------------------------------------
extern "C" void kernel_launch(void* const* d_in, const int* in_sizes, int n_in,
                              void* d_out, int out_size) {
    (void)in_sizes; (void)n_in; (void)out_size;
    const float* x  = (const float*)d_in[0];
    const float* wq = (const float*)d_in[1];
    const float* bq = (const float*)d_in[2];
    const float* wk = (const float*)d_in[3];
    const float* bk = (const float*)d_in[4];
    const float* wv = (const float*)d_in[5];
    const float* bv = (const float*)d_in[6];
    const float* wo = (const float*)d_in[7];
    const float* bo = (const float*)d_in[8];
    float* out = (float*)d_out;

    float *Q, *K, *V, *attn;
    cudaGetSymbolAddress((void**)&Q,    g_Q);
    cudaGetSymbolAddress((void**)&K,    g_K);
    cudaGetSymbolAddress((void**)&V,    g_V);
    cudaGetSymbolAddress((void**)&attn, g_attn);

    cudaFuncSetAttribute(gemm_tc, cudaFuncAttributeMaxDynamicSharedMemorySize,
                         GEMM_SMEM_BYTES);
    cudaFuncSetAttribute(scores_mma, cudaFuncAttributeMaxDynamicSharedMemorySize,
                         SCORES_SMEM);

    dim3 gg(D_ / 128, M_ / 128);   // (16, 32)
    gemm_tc<<<gg, 256, GEMM_SMEM_BYTES>>>(x, wq, bq, Q);
    gemm_tc<<<gg, 256, GEMM_SMEM_BYTES>>>(x, wk, bk, K);
    gemm_tc<<<gg, 256, GEMM_SMEM_BYTES>>>(x, wv, bv, V);

    scores_mma<<<dim3(S_ / 64, BH_), 256, SCORES_SMEM>>>(Q, K);

    chunk_sum_kernel<<<dim3(NCH, BH_), HD_>>>(V);
    prefix_kernel<<<BH_, HD_>>>();
    attn_kernel<<<dim3(NCH, BH_), HD_>>>(V, attn);

    gemm_tc<<<gg, 256, GEMM_SMEM_BYTES>>>(attn, wo, bo, out);
}